// round 1
// baseline (speedup 1.0000x reference)
#include <cuda_runtime.h>
#include <math.h>

#define NN 50000
#define NE 800000
#define NG 64
#define NE2 (NE + NN)

// ---------------- static scratch (no allocations allowed) ----------------
__device__ __align__(16) float  g_h1[NN * 128];    // x@W1
__device__ __align__(16) float  g_out1[NN * 128];  // elu(conv1 out + b1)
__device__ __align__(16) float  g_h2[NN * 32];     // out1@W2
__device__ float4 g_alpha1[NE2];                   // per-edge alpha, 4 heads
__device__ float  g_alpha2[NE2];
__device__ float  g_als1[NN * 4];
__device__ float  g_ald1[NN * 4];
__device__ float  g_als2[NN];
__device__ float  g_ald2[NN];
__device__ float  g_cnt[NN];
__device__ float  g_loop[NN * 8];
__device__ int    g_off[NN + 1];
__device__ int    g_cursor[NN];
__device__ int    g_csr[NE2];
__device__ float  g_ae1[32];   // [8][4] folded We1 * att_e1
__device__ float  g_ae2[8];    // folded We2 * att_e2
__device__ float  g_gsum[NG * 32];
__device__ float  g_gcnt[NG];

__device__ __forceinline__ float leaky(float a) { return a > 0.f ? a : 0.2f * a; }
__device__ __forceinline__ float elu(float a)   { return a > 0.f ? a : expm1f(a); }

// ---------------- zero the atomic accumulators ----------------
__global__ void k_zero() {
    int i = blockIdx.x * blockDim.x + threadIdx.x;
    if (i < NN * 8) g_loop[i] = 0.f;
    if (i < NN) { g_cnt[i] = 0.f; g_cursor[i] = 0; }
    if (i < NG * 32) g_gsum[i] = 0.f;
    if (i < NG) g_gcnt[i] = 0.f;
}

// ---------------- degree count + self-loop attr sums ----------------
__global__ void k_degree(const int* __restrict__ ei, const float* __restrict__ ea) {
    int e = blockIdx.x * blockDim.x + threadIdx.x;
    if (e >= NE) return;
    int d = ei[NE + e];
    atomicAdd(&g_cnt[d], 1.f);
    #pragma unroll
    for (int j = 0; j < 8; j++) atomicAdd(&g_loop[d * 8 + j], ea[e * 8 + j]);
}

__global__ void k_loopdiv() {
    int i = blockIdx.x * blockDim.x + threadIdx.x;
    if (i >= NN * 8) return;
    g_loop[i] /= fmaxf(g_cnt[i >> 3], 1.f);
}

// ---------------- single-block exclusive scan of degrees (+1 self loop) ----------------
__global__ void k_scan() {
    __shared__ int swsum[32];
    __shared__ int scarry;
    int t = threadIdx.x;
    int lane = t & 31, wid = t >> 5;
    if (t == 0) { scarry = 0; g_off[0] = 0; }
    __syncthreads();
    for (int base = 0; base < NN; base += 1024) {
        int i = base + t;
        int v = (i < NN) ? (int)g_cnt[i] + 1 : 0;
        int s = v;
        #pragma unroll
        for (int o = 1; o < 32; o <<= 1) {
            int u = __shfl_up_sync(0xffffffffu, s, o);
            if (lane >= o) s += u;
        }
        if (lane == 31) swsum[wid] = s;
        __syncthreads();
        if (wid == 0) {
            int w = swsum[lane];
            #pragma unroll
            for (int o = 1; o < 32; o <<= 1) {
                int u = __shfl_up_sync(0xffffffffu, w, o);
                if (lane >= o) w += u;
            }
            swsum[lane] = w;
        }
        __syncthreads();
        int prefix = scarry + (wid > 0 ? swsum[wid - 1] : 0);
        if (i < NN) g_off[i + 1] = prefix + s;
        __syncthreads();
        if (t == 0) scarry += swsum[31];
        __syncthreads();
    }
}

// ---------------- CSR fill (edge ids grouped by dst; id>=NE encodes self-loop) ----------------
__global__ void k_fill(const int* __restrict__ ei) {
    int i = blockIdx.x * blockDim.x + threadIdx.x;
    if (i >= NE2) return;
    int d = (i < NE) ? ei[NE + i] : (i - NE);
    int pos = g_off[d] + atomicAdd(&g_cursor[d], 1);
    g_csr[pos] = i;
}

// ---------------- fold We * att_e (tiny) ----------------
__global__ void k_ae(const float* __restrict__ We1, const float* __restrict__ ae1,
                     const float* __restrict__ We2, const float* __restrict__ ae2) {
    int t = threadIdx.x;
    if (t < 32) {
        int d = t >> 2, h = t & 3;
        float s = 0.f;
        for (int c = 0; c < 32; c++) s += We1[d * 128 + h * 32 + c] * ae1[h * 32 + c];
        g_ae1[d * 4 + h] = s;
    }
    if (t < 8) {
        float s = 0.f;
        for (int c = 0; c < 32; c++) s += We2[t * 32 + c] * ae2[c];
        g_ae2[t] = s;
    }
}

// ---------------- GEMM1: h1 = x @ W1   [50000,128]x[128,128] ----------------
__global__ void k_gemm1(const float* __restrict__ x, const float* __restrict__ W) {
    __shared__ __align__(16) float sA[64 * 16];
    __shared__ __align__(16) float sB[16 * 128];
    int t = threadIdx.x;
    int tx = t & 31, ty = t >> 5;       // warp=ty owns 8 rows, lane=tx owns 4 cols
    int n0 = blockIdx.x * 64;
    float acc[8][4];
    #pragma unroll
    for (int i = 0; i < 8; i++)
        #pragma unroll
        for (int j = 0; j < 4; j++) acc[i][j] = 0.f;

    for (int kc = 0; kc < 128; kc += 16) {
        { // A tile 64x16
            int row = t >> 2, c4 = t & 3;
            float4 v = make_float4(0.f, 0.f, 0.f, 0.f);
            if (n0 + row < NN) v = *(const float4*)&x[(n0 + row) * 128 + kc + c4 * 4];
            *(float4*)&sA[row * 16 + c4 * 4] = v;
        }
        #pragma unroll
        for (int r = 0; r < 2; r++) { // B tile 16x128
            int idx = t + r * 256;
            int row = idx >> 5, c4 = idx & 31;
            *(float4*)&sB[row * 128 + c4 * 4] = *(const float4*)&W[(kc + row) * 128 + c4 * 4];
        }
        __syncthreads();
        #pragma unroll
        for (int k = 0; k < 16; k++) {
            float4 bv = *(float4*)&sB[k * 128 + tx * 4];
            #pragma unroll
            for (int i = 0; i < 8; i++) {
                float av = sA[(ty * 8 + i) * 16 + k];
                acc[i][0] += av * bv.x; acc[i][1] += av * bv.y;
                acc[i][2] += av * bv.z; acc[i][3] += av * bv.w;
            }
        }
        __syncthreads();
    }
    #pragma unroll
    for (int i = 0; i < 8; i++) {
        int n = n0 + ty * 8 + i;
        if (n < NN)
            *(float4*)&g_h1[n * 128 + tx * 4] =
                make_float4(acc[i][0], acc[i][1], acc[i][2], acc[i][3]);
    }
}

// ---------------- attention dots for conv1: al_s, al_d [N,4] ----------------
__global__ void k_att1(const float* __restrict__ as1, const float* __restrict__ ad1) {
    int gw = (blockIdx.x * blockDim.x + threadIdx.x) >> 5;
    int lane = threadIdx.x & 31;
    if (gw >= NN) return;
    float s[4], d[4];
    #pragma unroll
    for (int r = 0; r < 4; r++) {
        float v = g_h1[gw * 128 + r * 32 + lane];
        s[r] = v * as1[r * 32 + lane];
        d[r] = v * ad1[r * 32 + lane];
    }
    #pragma unroll
    for (int o = 16; o; o >>= 1) {
        #pragma unroll
        for (int r = 0; r < 4; r++) {
            s[r] += __shfl_xor_sync(0xffffffffu, s[r], o);
            d[r] += __shfl_xor_sync(0xffffffffu, d[r], o);
        }
    }
    if (lane == 0) {
        #pragma unroll
        for (int r = 0; r < 4; r++) { g_als1[gw * 4 + r] = s[r]; g_ald1[gw * 4 + r] = d[r]; }
    }
}

// ---------------- per-edge alpha for conv1 ----------------
__global__ void k_alpha1(const int* __restrict__ ei, const float* __restrict__ ea) {
    __shared__ float sae[32];
    if (threadIdx.x < 32) sae[threadIdx.x] = g_ae1[threadIdx.x];
    __syncthreads();
    int e = blockIdx.x * blockDim.x + threadIdx.x;
    if (e >= NE2) return;
    int s, d;
    const float* a;
    if (e < NE) { s = ei[e]; d = ei[NE + e]; a = ea + e * 8; }
    else        { s = d = e - NE; a = g_loop + (size_t)(e - NE) * 8; }
    float t0 = 0.f, t1 = 0.f, t2 = 0.f, t3 = 0.f;
    #pragma unroll
    for (int j = 0; j < 8; j++) {
        float av = a[j];
        t0 += av * sae[j * 4 + 0]; t1 += av * sae[j * 4 + 1];
        t2 += av * sae[j * 4 + 2]; t3 += av * sae[j * 4 + 3];
    }
    float4 al;
    al.x = leaky(g_als1[s * 4 + 0] + g_ald1[d * 4 + 0] + t0);
    al.y = leaky(g_als1[s * 4 + 1] + g_ald1[d * 4 + 1] + t1);
    al.z = leaky(g_als1[s * 4 + 2] + g_ald1[d * 4 + 2] + t2);
    al.w = leaky(g_als1[s * 4 + 3] + g_ald1[d * 4 + 3] + t3);
    g_alpha1[e] = al;
}

// ---------------- conv1 aggregation: warp-per-node online softmax ----------------
__global__ void k_agg1(const int* __restrict__ ei, const float* __restrict__ b1) {
    int n = (blockIdx.x * blockDim.x + threadIdx.x) >> 5;
    int lane = threadIdx.x & 31;
    if (n >= NN) return;
    int beg = g_off[n], end = g_off[n + 1];
    float m[4], den[4], acc[4];
    #pragma unroll
    for (int r = 0; r < 4; r++) { m[r] = -1e30f; den[r] = 0.f; acc[r] = 0.f; }
    for (int j = beg; j < end; j++) {
        int eid = g_csr[j];
        int s = (eid < NE) ? ei[eid] : (eid - NE);
        float4 a4 = g_alpha1[eid];
        float av[4] = {a4.x, a4.y, a4.z, a4.w};
        const float* hrow = g_h1 + (size_t)s * 128 + lane;
        #pragma unroll
        for (int r = 0; r < 4; r++) {
            float aa = av[r];
            if (aa > m[r]) {
                float sc = __expf(m[r] - aa);
                den[r] *= sc; acc[r] *= sc; m[r] = aa;
            }
            float w = __expf(aa - m[r]);
            den[r] += w;
            acc[r] += w * hrow[r * 32];
        }
    }
    #pragma unroll
    for (int r = 0; r < 4; r++) {
        float o = acc[r] / (den[r] + 1e-16f) + b1[r * 32 + lane];
        g_out1[(size_t)n * 128 + r * 32 + lane] = elu(o);
    }
}

// ---------------- GEMM2: h2 = out1 @ W2  [N,128]x[128,32], fused att dots ----------------
__global__ void k_gemm2(const float* __restrict__ W2,
                        const float* __restrict__ as2, const float* __restrict__ ad2) {
    __shared__ __align__(16) float sA[64 * 32];
    __shared__ __align__(16) float sB[32 * 32];
    int t = threadIdx.x;
    int tx = t & 31, ty = t >> 5;
    int n0 = blockIdx.x * 64;
    float acc[8];
    #pragma unroll
    for (int i = 0; i < 8; i++) acc[i] = 0.f;

    for (int kc = 0; kc < 128; kc += 32) {
        #pragma unroll
        for (int r = 0; r < 2; r++) {
            int idx = t + r * 256;
            int row = idx >> 3, c4 = idx & 7;
            float4 v = make_float4(0.f, 0.f, 0.f, 0.f);
            if (n0 + row < NN) v = *(const float4*)&g_out1[(size_t)(n0 + row) * 128 + kc + c4 * 4];
            *(float4*)&sA[row * 32 + c4 * 4] = v;
        }
        {
            int row = t >> 3, c4 = t & 7;
            *(float4*)&sB[row * 32 + c4 * 4] = *(const float4*)&W2[(kc + row) * 32 + c4 * 4];
        }
        __syncthreads();
        #pragma unroll
        for (int k = 0; k < 32; k++) {
            float bv = sB[k * 32 + tx];
            #pragma unroll
            for (int i = 0; i < 8; i++) acc[i] += sA[(ty * 8 + i) * 32 + k] * bv;
        }
        __syncthreads();
    }
    float aS = as2[tx], aD = ad2[tx];
    #pragma unroll
    for (int i = 0; i < 8; i++) {
        int n = n0 + ty * 8 + i;
        if (n < NN) {
            g_h2[(size_t)n * 32 + tx] = acc[i];
            float ps = acc[i] * aS, pd = acc[i] * aD;
            #pragma unroll
            for (int o = 16; o; o >>= 1) {
                ps += __shfl_xor_sync(0xffffffffu, ps, o);
                pd += __shfl_xor_sync(0xffffffffu, pd, o);
            }
            if (tx == 0) { g_als2[n] = ps; g_ald2[n] = pd; }
        }
    }
}

// ---------------- per-edge alpha for conv2 ----------------
__global__ void k_alpha2(const int* __restrict__ ei, const float* __restrict__ ea) {
    __shared__ float sae[8];
    if (threadIdx.x < 8) sae[threadIdx.x] = g_ae2[threadIdx.x];
    __syncthreads();
    int e = blockIdx.x * blockDim.x + threadIdx.x;
    if (e >= NE2) return;
    int s, d;
    const float* a;
    if (e < NE) { s = ei[e]; d = ei[NE + e]; a = ea + e * 8; }
    else        { s = d = e - NE; a = g_loop + (size_t)(e - NE) * 8; }
    float tt = 0.f;
    #pragma unroll
    for (int j = 0; j < 8; j++) tt += a[j] * sae[j];
    g_alpha2[e] = leaky(g_als2[s] + g_ald2[d] + tt);
}

// ---------------- conv2 aggregation + fused mean-pool accumulation ----------------
__global__ void k_agg2(const int* __restrict__ ei, const float* __restrict__ b2,
                       const int* __restrict__ batch) {
    int n = (blockIdx.x * blockDim.x + threadIdx.x) >> 5;
    int lane = threadIdx.x & 31;
    if (n >= NN) return;
    int beg = g_off[n], end = g_off[n + 1];
    float m = -1e30f, den = 0.f, acc = 0.f;
    for (int j = beg; j < end; j++) {
        int eid = g_csr[j];
        int s = (eid < NE) ? ei[eid] : (eid - NE);
        float aa = g_alpha2[eid];
        if (aa > m) {
            float sc = __expf(m - aa);
            den *= sc; acc *= sc; m = aa;
        }
        float w = __expf(aa - m);
        den += w;
        acc += w * g_h2[(size_t)s * 32 + lane];
    }
    float val = elu(acc / (den + 1e-16f) + b2[lane]);
    int b = batch[n];
    atomicAdd(&g_gsum[b * 32 + lane], val);
    if (lane == 0) atomicAdd(&g_gcnt[b], 1.f);
}

// ---------------- final MLP head ----------------
__global__ void k_final(const float* __restrict__ W3, const float* __restrict__ b3,
                        const float* __restrict__ W4, const float* __restrict__ b4,
                        float* __restrict__ out) {
    int t = threadIdx.x;
    if (t >= NG) return;
    float c = fmaxf(g_gcnt[t], 1.f);
    float g[32];
    #pragma unroll
    for (int i = 0; i < 32; i++) g[i] = g_gsum[t * 32 + i] / c;
    float z[16];
    #pragma unroll
    for (int j = 0; j < 16; j++) {
        float s = b3[j];
        #pragma unroll
        for (int i = 0; i < 32; i++) s += g[i] * W3[i * 16 + j];
        z[j] = fmaxf(s, 0.f);
    }
    #pragma unroll
    for (int o = 0; o < 10; o++) {
        float s = b4[o];
        #pragma unroll
        for (int j = 0; j < 16; j++) s += z[j] * W4[j * 10 + o];
        out[t * 10 + o] = s;
    }
}

extern "C" void kernel_launch(void* const* d_in, const int* in_sizes, int n_in,
                              void* d_out, int out_size) {
    const float* x     = (const float*)d_in[0];
    const int*   ei    = (const int*)d_in[1];
    const float* ea    = (const float*)d_in[2];
    const int*   batch = (const int*)d_in[3];
    const float* W1    = (const float*)d_in[4];
    const float* as1   = (const float*)d_in[5];
    const float* ad1   = (const float*)d_in[6];
    const float* We1   = (const float*)d_in[7];
    const float* ae1   = (const float*)d_in[8];
    const float* b1    = (const float*)d_in[9];
    const float* W2    = (const float*)d_in[10];
    const float* as2   = (const float*)d_in[11];
    const float* ad2   = (const float*)d_in[12];
    const float* We2   = (const float*)d_in[13];
    const float* ae2   = (const float*)d_in[14];
    const float* b2    = (const float*)d_in[15];
    const float* W3    = (const float*)d_in[16];
    const float* b3    = (const float*)d_in[17];
    const float* W4    = (const float*)d_in[18];
    const float* b4    = (const float*)d_in[19];
    float* out = (float*)d_out;

    k_zero   <<<(NN * 8 + 255) / 256, 256>>>();
    k_degree <<<(NE + 255) / 256, 256>>>(ei, ea);
    k_loopdiv<<<(NN * 8 + 255) / 256, 256>>>();
    k_scan   <<<1, 1024>>>();
    k_fill   <<<(NE2 + 255) / 256, 256>>>(ei);
    k_ae     <<<1, 32>>>(We1, ae1, We2, ae2);
    k_gemm1  <<<(NN + 63) / 64, 256>>>(x, W1);
    k_att1   <<<(NN + 7) / 8, 256>>>(as1, ad1);
    k_alpha1 <<<(NE2 + 255) / 256, 256>>>(ei, ea);
    k_agg1   <<<(NN + 7) / 8, 256>>>(ei, b1);
    k_gemm2  <<<(NN + 63) / 64, 256>>>(W2, as2, ad2);
    k_alpha2 <<<(NE2 + 255) / 256, 256>>>(ei, ea);
    k_agg2   <<<(NN + 7) / 8, 256>>>(ei, b2, batch);
    k_final  <<<1, 64>>>(W3, b3, W4, b4, out);
}